// round 7
// baseline (speedup 1.0000x reference)
#include <cuda_runtime.h>
#include <cuda_bf16.h>
#include <cstdint>
#include <math.h>

#define EPS   1e-5f
#define BB    2
#define NN    512
#define DD    64

typedef unsigned long long ull;
typedef unsigned int u32;

// ---------------- device scratch ----------------
__device__ __align__(16) float g_U   [BB*NN*128];   // s1*(W1a@f), [node][128]
__device__ __align__(16) float g_V   [BB*NN*128];   // s1*(W1b@f)+bias, [node][128]
__device__ __align__(16) float g_nfn [BB*NN*DD];
__device__ __align__(16) uint4 g_W2f [8*8*32];      // B-frag bf16: {bh0,bh1,bl0,bl1}
__device__ __align__(16) uint4 g_W3f [4*4*32];
__device__ float g_c2[64], g_c3[32], g_w4[32], g_b4s;
__device__ int   g_active[BB];

// ---------------- helpers ----------------
__device__ __forceinline__ u32 pk(float e0, float e1) {
    u32 r; asm("cvt.rn.bf16x2.f32 %0, %1, %2;" : "=r"(r) : "f"(e1), "f"(e0)); return r;
}
__device__ __forceinline__ u32 pk_res(float e0, float e1, u32 h) {
    float r0 = __uint_as_float(h << 16);
    float r1 = __uint_as_float(h & 0xffff0000u);
    return pk(e0 - r0, e1 - r1);
}
__device__ __forceinline__ void mma16(float c[4], u32 a0, u32 a1, u32 a2, u32 a3,
                                      u32 b0, u32 b1) {
    asm("mma.sync.aligned.m16n8k16.row.col.f32.bf16.bf16.f32 "
        "{%0,%1,%2,%3}, {%4,%5,%6,%7}, {%8,%9}, {%0,%1,%2,%3};"
        : "+f"(c[0]), "+f"(c[1]), "+f"(c[2]), "+f"(c[3])
        : "r"(a0), "r"(a1), "r"(a2), "r"(a3), "r"(b0), "r"(b1));
}

// ---------------- smem layout (bytes) ----------------
#define OFF_W2F  0          /* 32768 */
#define OFF_W3F  32768      /* 8192  */
#define OFF_UI   40960      /* 16*128*4 = 8192 */
#define OFF_UJ   49152      /* 8192 */
#define OFF_VI   57344      /* 16*132*4 = 8448 */
#define OFF_VJ   65792      /* 8448 */
#define OFF_NFI  74240      /* 16*68*4 = 4352 */
#define OFF_NFJ  78592      /* 4352 */
#define OFF_LS   82944      /* 2*16*16*4 = 2048 */
#define OFF_C2   84992      /* 256 */
#define OFF_C3   85248      /* 128 */
#define OFF_W4   85376      /* 128 */
#define OFF_B4   85504      /* 4 */
#define OFF_MI   85512      /* 16*4 */
#define OFF_MJ   85576      /* 16*4 */
#define OFF_ACT  85640      /* 4 */
#define SMEM_MM  85648

// ---------------- merged prep: nodes + weight packing + consts + active ----
__global__ void k_prep(const float* __restrict__ f,
                       const float* __restrict__ W1, const float* __restrict__ b1,
                       const float* __restrict__ g1, const float* __restrict__ be1,
                       const float* __restrict__ m1, const float* __restrict__ v1,
                       const float* __restrict__ W2, const float* __restrict__ b2,
                       const float* __restrict__ g2, const float* __restrict__ be2,
                       const float* __restrict__ m2, const float* __restrict__ v2,
                       const float* __restrict__ W3, const float* __restrict__ b3,
                       const float* __restrict__ g3, const float* __restrict__ be3,
                       const float* __restrict__ m3, const float* __restrict__ v3,
                       const float* __restrict__ W4, const float* __restrict__ b4,
                       const int* __restrict__ masks) {
    int t = threadIdx.x;
    int bid = blockIdx.x;
    if (bid < BB * NN) {
        // ---- per-node U, V, normalized features ----
        __shared__ float fs[DD];
        __shared__ float sinv;
        int node = bid;
        if (t < DD) fs[t] = f[node * DD + t];
        __syncthreads();
        if (t == 0) {
            float ss = 0.f;
            for (int d = 0; d < DD; d++) ss += fs[d] * fs[d];
            sinv = 1.f / fmaxf(sqrtf(ss), 1e-12f);
        }
        __syncthreads();
        if (t < DD) g_nfn[node * DD + t] = fs[t] * sinv;

        float s1 = g1[t] * rsqrtf(v1[t] + EPS);
        float u = 0.f, vv = 0.f;
        const float* wr = &W1[t * 128];
        #pragma unroll 8
        for (int d = 0; d < DD; d++) {
            u  += wr[d]      * fs[d];
            vv += wr[DD + d] * fs[d];
        }
        g_U[node * 128 + t] = u * s1;
        g_V[node * 128 + t] = vv * s1 + (b1[t] - m1[t]) * s1 + be1[t];
        return;
    }
    int fb = bid - BB * NN;     // 0..7
    // ---- W2 B-frags (2048 entries) ----
    for (int idx = fb * 128 + t; idx < 8 * 8 * 32; idx += 1024) {
        int ks = idx >> 8, nt = (idx >> 5) & 7, l = idx & 31;
        int n = 8 * nt + (l >> 2), k0 = 16 * ks + 2 * (l & 3);
        float s = g2[n] * rsqrtf(v2[n] + EPS);
        float w00 = W2[n * 128 + k0] * s,     w01 = W2[n * 128 + k0 + 1] * s;
        float w10 = W2[n * 128 + k0 + 8] * s, w11 = W2[n * 128 + k0 + 9] * s;
        u32 bh0 = pk(w00, w01), bh1 = pk(w10, w11);
        g_W2f[idx] = make_uint4(bh0, bh1, pk_res(w00, w01, bh0), pk_res(w10, w11, bh1));
    }
    // ---- W3 B-frags (512 entries, blocks 0..3) ----
    {
        int idx = fb * 128 + t;
        if (idx < 4 * 4 * 32) {
            int ks = idx >> 7, nt = (idx >> 5) & 3, l = idx & 31;
            int n = 8 * nt + (l >> 2), k0 = 16 * ks + 2 * (l & 3);
            float s = g3[n] * rsqrtf(v3[n] + EPS);
            float w00 = W3[n * 64 + k0] * s,     w01 = W3[n * 64 + k0 + 1] * s;
            float w10 = W3[n * 64 + k0 + 8] * s, w11 = W3[n * 64 + k0 + 9] * s;
            u32 bh0 = pk(w00, w01), bh1 = pk(w10, w11);
            g_W3f[idx] = make_uint4(bh0, bh1, pk_res(w00, w01, bh0), pk_res(w10, w11, bh1));
        }
    }
    if (fb == 4) {
        if (t < 64) {
            float s = g2[t] * rsqrtf(v2[t] + EPS);
            g_c2[t] = (b2[t] - m2[t]) * s + be2[t];
        } else if (t < 96) {
            int o = t - 64;
            float s = g3[o] * rsqrtf(v3[o] + EPS);
            g_c3[o] = (b3[o] - m3[o]) * s + be3[o];
        } else {
            g_w4[t - 96] = W4[t - 96];
        }
    }
    if (fb == 5) {
        __shared__ int cnt[BB];
        if (t < BB) cnt[t] = 0;
        __syncthreads();
        for (int idx = t; idx < BB * NN; idx += 128)
            if (masks[idx] != 0) atomicAdd(&cnt[idx / NN], 1);
        __syncthreads();
        if (t < BB) g_active[t] = (cnt[t] > 1) ? 1 : 0;
        if (t == 64) g_b4s = b4[0];
    }
}

// ---------------- main: fused MLP + epilogue, mirrored 16x16 tile pairs ----
// Jobs: (b, I<=J) over 32x32 macro-tiles; 528 per b, 1056 total.
// Per job: compute L-tile (I,J) [+ (J,I) if I!=J], then inline
// symmetrize + cosine sim + sigmoid + mask, write both orientations.
__global__ __launch_bounds__(256, 2)
void k_pair(const int* __restrict__ masks, float* __restrict__ out,
            int write_logits) {
    extern __shared__ __align__(16) char sm[];
    uint4* W2s = (uint4*)(sm + OFF_W2F);
    uint4* W3s = (uint4*)(sm + OFF_W3F);
    float* UI  = (float*)(sm + OFF_UI);
    float* UJ  = (float*)(sm + OFF_UJ);
    float* VI  = (float*)(sm + OFF_VI);   // stride 132
    float* VJ  = (float*)(sm + OFF_VJ);
    float* NFI = (float*)(sm + OFF_NFI);  // stride 68
    float* NFJ = (float*)(sm + OFF_NFJ);
    float* Ls  = (float*)(sm + OFF_LS);   // [2][16][16]
    float* c2s = (float*)(sm + OFF_C2);
    float* c3s = (float*)(sm + OFF_C3);
    float* w4s = (float*)(sm + OFF_W4);
    float* b4s = (float*)(sm + OFF_B4);
    int*   mI  = (int*)  (sm + OFF_MI);
    int*   mJ  = (int*)  (sm + OFF_MJ);
    int*   act = (int*)  (sm + OFF_ACT);

    int t = threadIdx.x;
    int w = t >> 5, l = t & 31;
    int tg = l & 3, gid = l >> 2;

    {
        const uint4* s4 = (const uint4*)g_W2f;
        for (int i = t; i < 8 * 8 * 32; i += 256) W2s[i] = s4[i];
        const uint4* s3 = (const uint4*)g_W3f;
        for (int i = t; i < 4 * 4 * 32; i += 256) W3s[i] = s3[i];
        if (t < 64) c2s[t] = g_c2[t];
        if (t < 32) { c3s[t] = g_c3[t]; w4s[t] = g_w4[t]; }
        if (t == 0) b4s[0] = g_b4s;
    }
    __syncthreads();

    const int NJOB = BB * 528;
    for (int jid = blockIdx.x; jid < NJOB; jid += gridDim.x) {
        int b = jid / 528;
        int r = jid % 528;
        int I = 0;
        while (r >= 32 - I) { r -= (32 - I); I++; }
        int J = I + r;
        bool diag = (I == J);
        int I0 = I << 4, J0 = J << 4;

        // ---- stage U/V/NF tiles (one big granule) ----
        {
            const float4* uI4 = (const float4*)&g_U[((size_t)b * NN + I0) * 128];
            const float4* uJ4 = (const float4*)&g_U[((size_t)b * NN + J0) * 128];
            ((float4*)UI)[t] = uI4[t];           ((float4*)UI)[t + 256] = uI4[t + 256];
            ((float4*)UJ)[t] = uJ4[t];           ((float4*)UJ)[t + 256] = uJ4[t + 256];
            #pragma unroll
            for (int q = 0; q < 2; q++) {
                int idx = t + q * 256;
                int jj = idx >> 5, kq = idx & 31;
                float4 vi = ((const float4*)&g_V[((size_t)b * NN + I0 + jj) * 128])[kq];
                float4 vj = ((const float4*)&g_V[((size_t)b * NN + J0 + jj) * 128])[kq];
                *(float4*)&VI[jj * 132 + kq * 4] = vi;
                *(float4*)&VJ[jj * 132 + kq * 4] = vj;
            }
            {
                int row = t >> 4, q = t & 15;
                float4 ni = ((const float4*)&g_nfn[((size_t)b * NN + I0 + row) * DD])[q];
                float4 nj = ((const float4*)&g_nfn[((size_t)b * NN + J0 + row) * DD])[q];
                *(float4*)&NFI[row * 68 + q * 4] = ni;
                *(float4*)&NFJ[row * 68 + q * 4] = nj;
            }
            if (t < 16) mI[t] = masks[b * NN + I0 + t];
            else if (t < 32) mJ[t - 16] = masks[b * NN + J0 + (t - 16)];
            else if (t == 32) act[0] = g_active[b];
        }
        __syncthreads();

        // ---- GEMM row-jobs: rows 0..15 = tile0 (i in I, j in J), 16..31 = tile1 ----
        int nrj = diag ? 2 : 4;
        for (int rj = 0; rj < nrj; rj++) {
            int row = w + 8 * rj;
            int tileIdx = row >> 4;
            int irow = row & 15;
            const float* urow = (tileIdx == 0 ? UI : UJ) + irow * 128;
            const float* Vt   = (tileIdx == 0 ? VJ : VI);

            float cA[8][4];
            #pragma unroll
            for (int nt = 0; nt < 8; nt++)
                #pragma unroll
                for (int q = 0; q < 4; q++) cA[nt][q] = 0.f;

            #pragma unroll
            for (int ks = 0; ks < 8; ks++) {
                int k0 = 16 * ks + 2 * tg;
                float2 uA  = *(const float2*)&urow[k0];
                float2 uB  = *(const float2*)&urow[k0 + 8];
                float2 v0A = *(const float2*)&Vt[gid * 132 + k0];
                float2 v1A = *(const float2*)&Vt[(gid + 8) * 132 + k0];
                float2 v0B = *(const float2*)&Vt[gid * 132 + k0 + 8];
                float2 v1B = *(const float2*)&Vt[(gid + 8) * 132 + k0 + 8];
                float e00 = fmaxf(uA.x + v0A.x, 0.f), e01 = fmaxf(uA.y + v0A.y, 0.f);
                float e10 = fmaxf(uA.x + v1A.x, 0.f), e11 = fmaxf(uA.y + v1A.y, 0.f);
                float e20 = fmaxf(uB.x + v0B.x, 0.f), e21 = fmaxf(uB.y + v0B.y, 0.f);
                float e30 = fmaxf(uB.x + v1B.x, 0.f), e31 = fmaxf(uB.y + v1B.y, 0.f);
                u32 a0h = pk(e00, e01), a1h = pk(e10, e11);
                u32 a2h = pk(e20, e21), a3h = pk(e30, e31);
                u32 a0l = pk_res(e00, e01, a0h), a1l = pk_res(e10, e11, a1h);
                u32 a2l = pk_res(e20, e21, a2h), a3l = pk_res(e30, e31, a3h);
                #pragma unroll
                for (int nt = 0; nt < 8; nt++) {
                    uint4 B = W2s[(ks * 8 + nt) * 32 + l];
                    mma16(cA[nt], a0h, a1h, a2h, a3h, B.x, B.y);
                    mma16(cA[nt], a0l, a1l, a2l, a3l, B.x, B.y);
                    mma16(cA[nt], a0h, a1h, a2h, a3h, B.z, B.w);
                }
            }

            float cB[4][4];
            #pragma unroll
            for (int nt = 0; nt < 4; nt++)
                #pragma unroll
                for (int q = 0; q < 4; q++) cB[nt][q] = 0.f;

            #pragma unroll
            for (int ks = 0; ks < 4; ks++) {
                int n0 = 2 * ks, n1 = n0 + 1;
                float cb00 = c2s[8 * n0 + 2 * tg], cb01 = c2s[8 * n0 + 2 * tg + 1];
                float cb10 = c2s[8 * n1 + 2 * tg], cb11 = c2s[8 * n1 + 2 * tg + 1];
                float e00 = fmaxf(cA[n0][0] + cb00, 0.f), e01 = fmaxf(cA[n0][1] + cb01, 0.f);
                float e10 = fmaxf(cA[n0][2] + cb00, 0.f), e11 = fmaxf(cA[n0][3] + cb01, 0.f);
                float e20 = fmaxf(cA[n1][0] + cb10, 0.f), e21 = fmaxf(cA[n1][1] + cb11, 0.f);
                float e30 = fmaxf(cA[n1][2] + cb10, 0.f), e31 = fmaxf(cA[n1][3] + cb11, 0.f);
                u32 a0h = pk(e00, e01), a1h = pk(e10, e11);
                u32 a2h = pk(e20, e21), a3h = pk(e30, e31);
                u32 a0l = pk_res(e00, e01, a0h), a1l = pk_res(e10, e11, a1h);
                u32 a2l = pk_res(e20, e21, a2h), a3l = pk_res(e30, e31, a3h);
                #pragma unroll
                for (int nt = 0; nt < 4; nt++) {
                    uint4 B = W3s[(ks * 4 + nt) * 32 + l];
                    mma16(cB[nt], a0h, a1h, a2h, a3h, B.x, B.y);
                    mma16(cB[nt], a0l, a1l, a2l, a3l, B.x, B.y);
                    mma16(cB[nt], a0h, a1h, a2h, a3h, B.z, B.w);
                }
            }

            float pl = 0.f, ph = 0.f;
            #pragma unroll
            for (int nt = 0; nt < 4; nt++) {
                int c0 = 8 * nt + 2 * tg, c1 = c0 + 1;
                float w0 = w4s[c0], w1 = w4s[c1];
                float b0 = c3s[c0], b1 = c3s[c1];
                pl += fmaxf(cB[nt][0] + b0, 0.f) * w0 + fmaxf(cB[nt][1] + b1, 0.f) * w1;
                ph += fmaxf(cB[nt][2] + b0, 0.f) * w0 + fmaxf(cB[nt][3] + b1, 0.f) * w1;
            }
            pl += __shfl_xor_sync(0xffffffffu, pl, 1);
            pl += __shfl_xor_sync(0xffffffffu, pl, 2);
            ph += __shfl_xor_sync(0xffffffffu, ph, 1);
            ph += __shfl_xor_sync(0xffffffffu, ph, 2);
            if (tg == 0) {
                float base = b4s[0];
                Ls[tileIdx * 256 + irow * 16 + gid]     = base + pl;
                Ls[tileIdx * 256 + irow * 16 + gid + 8] = base + ph;
            }
        }
        __syncthreads();

        // ---- inline epilogue: 256 sym values, write both orientations ----
        {
            int ii = t >> 4, jj = t & 15;
            float l01 = Ls[ii * 16 + jj];
            float l10 = diag ? Ls[jj * 16 + ii] : Ls[256 + jj * 16 + ii];
            int ig = I0 + ii, jg = J0 + jj;
            float lsym = (ig == jg) ? -10.f : 0.5f * (l01 + l10);

            float sim = 0.f;
            const float* nfi = &NFI[ii * 68];
            const float* nfj = &NFJ[jj * 68];
            #pragma unroll
            for (int d = 0; d < DD; d += 4) {
                float4 x = *(const float4*)&nfi[d];
                float4 y = *(const float4*)&nfj[d];
                sim += x.x * y.x + x.y * y.y + x.z * y.z + x.w * y.w;
            }

            float logit = (lsym + 2.f * sim) * 2.f;
            float p = 1.f / (1.f + expf(-logit));
            p = (p > 0.6f) ? p * 1.2f : p * 0.8f;
            p = fminf(fmaxf(p, 0.f), 1.f);

            bool m = (mI[ii] != 0) && (mJ[jj] != 0) && (act[0] != 0);
            float pv = m ? p : 0.f;
            float lv = m ? logit : 0.f;
            size_t idx  = ((size_t)b * NN + ig) * NN + jg;
            size_t idxT = ((size_t)b * NN + jg) * NN + ig;
            out[idx]  = pv;
            out[idxT] = pv;
            if (write_logits) {
                out[(size_t)BB * NN * NN + idx]  = lv;
                out[(size_t)BB * NN * NN + idxT] = lv;
            }
        }
        __syncthreads();
    }
}

// ---------------- launch ----------------
extern "C" void kernel_launch(void* const* d_in, const int* in_sizes, int n_in,
                              void* d_out, int out_size) {
    const float* nf    = (const float*)d_in[0];
    const int*   masks = (const int*)  d_in[1];
    const float *W1, *b1, *W2, *b2, *W3, *b3, *W4, *b4;
    const float *g1, *be1, *m1, *v1, *g2, *be2, *m2, *v2, *g3, *be3, *m3, *v3;

    if (n_in >= 22 && in_sizes[4] == 8192) {
        W1 = (const float*)d_in[2];  b1 = (const float*)d_in[3];
        W2 = (const float*)d_in[4];  b2 = (const float*)d_in[5];
        W3 = (const float*)d_in[6];  b3 = (const float*)d_in[7];
        W4 = (const float*)d_in[8];  b4 = (const float*)d_in[9];
        g1 = (const float*)d_in[10]; be1 = (const float*)d_in[11];
        m1 = (const float*)d_in[12]; v1  = (const float*)d_in[13];
        g2 = (const float*)d_in[14]; be2 = (const float*)d_in[15];
        m2 = (const float*)d_in[16]; v2  = (const float*)d_in[17];
        g3 = (const float*)d_in[18]; be3 = (const float*)d_in[19];
        m3 = (const float*)d_in[20]; v3  = (const float*)d_in[21];
    } else {
        W1 = (const float*)d_in[2];  b1 = (const float*)d_in[3];
        g1 = (const float*)d_in[4];  be1 = (const float*)d_in[5];
        m1 = (const float*)d_in[6];  v1  = (const float*)d_in[7];
        W2 = (const float*)d_in[8];  b2 = (const float*)d_in[9];
        g2 = (const float*)d_in[10]; be2 = (const float*)d_in[11];
        m2 = (const float*)d_in[12]; v2  = (const float*)d_in[13];
        W3 = (const float*)d_in[14]; b3 = (const float*)d_in[15];
        g3 = (const float*)d_in[16]; be3 = (const float*)d_in[17];
        m3 = (const float*)d_in[18]; v3  = (const float*)d_in[19];
        W4 = (const float*)d_in[20]; b4 = (const float*)d_in[21];
    }

    static bool attr_set = false;
    if (!attr_set) {
        cudaFuncSetAttribute(k_pair, cudaFuncAttributeMaxDynamicSharedMemorySize, SMEM_MM);
        attr_set = true;
    }

    k_prep<<<BB * NN + 8, 128>>>(nf, W1, b1, g1, be1, m1, v1,
                                 W2, b2, g2, be2, m2, v2,
                                 W3, b3, g3, be3, m3, v3, W4, b4, masks);
    int wl = (out_size >= 2 * BB * NN * NN) ? 1 : 0;
    k_pair<<<296, 256, SMEM_MM>>>(masks, (float*)d_out, wl);
}

// round 8
// speedup vs baseline: 1.3962x; 1.3962x over previous
#include <cuda_runtime.h>
#include <cuda_bf16.h>
#include <cstdint>
#include <math.h>

#define EPS   1e-5f
#define BB    2
#define NN    512
#define DD    64

typedef unsigned long long ull;
typedef unsigned int u32;

// ---------------- device scratch ----------------
__device__ __align__(16) float g_U   [BB*NN*128];   // s1*(W1a@f), [node][128]
__device__ __align__(16) float g_V   [BB*NN*128];   // s1*(W1b@f)+bias, [node][128]
__device__ __align__(16) float g_nfn [BB*NN*DD];
__device__ __align__(16) uint4 g_W2f [8*8*32];      // B-frag bf16: {bh0,bh1,bl0,bl1}
__device__ __align__(16) uint4 g_W3f [4*4*32];
__device__ float g_c2[64], g_c3[32], g_w4[32], g_b4s;
__device__ __align__(16) float g_L   [BB*NN*NN];
__device__ int   g_active[BB];

// ---------------- helpers ----------------
__device__ __forceinline__ u32 pk(float e0, float e1) {
    u32 r; asm("cvt.rn.bf16x2.f32 %0, %1, %2;" : "=r"(r) : "f"(e1), "f"(e0)); return r;
}
__device__ __forceinline__ u32 pk_res(float e0, float e1, u32 h) {
    float r0 = __uint_as_float(h << 16);
    float r1 = __uint_as_float(h & 0xffff0000u);
    return pk(e0 - r0, e1 - r1);
}
__device__ __forceinline__ void mma16(float c[4], u32 a0, u32 a1, u32 a2, u32 a3,
                                      u32 b0, u32 b1) {
    asm("mma.sync.aligned.m16n8k16.row.col.f32.bf16.bf16.f32 "
        "{%0,%1,%2,%3}, {%4,%5,%6,%7}, {%8,%9}, {%0,%1,%2,%3};"
        : "+f"(c[0]), "+f"(c[1]), "+f"(c[2]), "+f"(c[3])
        : "r"(a0), "r"(a1), "r"(a2), "r"(a3), "r"(b0), "r"(b1));
}
__device__ __forceinline__ u32 s2u(const void* p) {
    u32 a;
    asm("{ .reg .u64 t; cvta.to.shared.u64 t, %1; cvt.u32.u64 %0, t; }" : "=r"(a) : "l"(p));
    return a;
}
__device__ __forceinline__ void cp16(u32 dst, const void* src) {
    asm volatile("cp.async.ca.shared.global [%0], [%1], 16;"
                 :: "r"(dst), "l"(__cvta_generic_to_global(src)) : "memory");
}
#define CP_COMMIT() asm volatile("cp.async.commit_group;" ::: "memory")
#define CP_WAIT(n)  asm volatile("cp.async.wait_group %0;" :: "n"(n) : "memory")

// ---------------- smem layout (bytes) ----------------
#define OFF_W2F  0          /* 32768 */
#define OFF_W3F  32768      /* 8192 */
#define OFF_US   40960      /* 2 bufs x 4096  = 8192  (8*128 f32)   */
#define OFF_VS   49152      /* 2 bufs x 8448  = 16896 (16*132 f32)  */
#define OFF_C2   66048      /* 256 */
#define OFF_C3   66304      /* 128 */
#define OFF_W4   66432      /* 128 */
#define OFF_B4   66560      /* 4 */
#define SMEM_MM  66576

// ---------------- merged prep: nodes + weight packing + consts + active ----
__global__ void k_prep(const float* __restrict__ f,
                       const float* __restrict__ W1, const float* __restrict__ b1,
                       const float* __restrict__ g1, const float* __restrict__ be1,
                       const float* __restrict__ m1, const float* __restrict__ v1,
                       const float* __restrict__ W2, const float* __restrict__ b2,
                       const float* __restrict__ g2, const float* __restrict__ be2,
                       const float* __restrict__ m2, const float* __restrict__ v2,
                       const float* __restrict__ W3, const float* __restrict__ b3,
                       const float* __restrict__ g3, const float* __restrict__ be3,
                       const float* __restrict__ m3, const float* __restrict__ v3,
                       const float* __restrict__ W4, const float* __restrict__ b4,
                       const int* __restrict__ masks) {
    int t = threadIdx.x;
    int bid = blockIdx.x;
    if (bid < BB * NN) {
        __shared__ float fs[DD];
        __shared__ float sinv;
        int node = bid;
        if (t < DD) fs[t] = f[node * DD + t];
        __syncthreads();
        if (t == 0) {
            float ss = 0.f;
            for (int d = 0; d < DD; d++) ss += fs[d] * fs[d];
            sinv = 1.f / fmaxf(sqrtf(ss), 1e-12f);
        }
        __syncthreads();
        if (t < DD) g_nfn[node * DD + t] = fs[t] * sinv;

        float s1 = g1[t] * rsqrtf(v1[t] + EPS);
        float u = 0.f, vv = 0.f;
        const float* wr = &W1[t * 128];
        #pragma unroll 8
        for (int d = 0; d < DD; d++) {
            u  += wr[d]      * fs[d];
            vv += wr[DD + d] * fs[d];
        }
        g_U[node * 128 + t] = u * s1;
        g_V[node * 128 + t] = vv * s1 + (b1[t] - m1[t]) * s1 + be1[t];
        return;
    }
    int fb = bid - BB * NN;     // 0..7
    for (int idx = fb * 128 + t; idx < 8 * 8 * 32; idx += 1024) {
        int ks = idx >> 8, nt = (idx >> 5) & 7, l = idx & 31;
        int n = 8 * nt + (l >> 2), k0 = 16 * ks + 2 * (l & 3);
        float s = g2[n] * rsqrtf(v2[n] + EPS);
        float w00 = W2[n * 128 + k0] * s,     w01 = W2[n * 128 + k0 + 1] * s;
        float w10 = W2[n * 128 + k0 + 8] * s, w11 = W2[n * 128 + k0 + 9] * s;
        u32 bh0 = pk(w00, w01), bh1 = pk(w10, w11);
        g_W2f[idx] = make_uint4(bh0, bh1, pk_res(w00, w01, bh0), pk_res(w10, w11, bh1));
    }
    {
        int idx = fb * 128 + t;
        if (idx < 4 * 4 * 32) {
            int ks = idx >> 7, nt = (idx >> 5) & 3, l = idx & 31;
            int n = 8 * nt + (l >> 2), k0 = 16 * ks + 2 * (l & 3);
            float s = g3[n] * rsqrtf(v3[n] + EPS);
            float w00 = W3[n * 64 + k0] * s,     w01 = W3[n * 64 + k0 + 1] * s;
            float w10 = W3[n * 64 + k0 + 8] * s, w11 = W3[n * 64 + k0 + 9] * s;
            u32 bh0 = pk(w00, w01), bh1 = pk(w10, w11);
            g_W3f[idx] = make_uint4(bh0, bh1, pk_res(w00, w01, bh0), pk_res(w10, w11, bh1));
        }
    }
    if (fb == 4) {
        if (t < 64) {
            float s = g2[t] * rsqrtf(v2[t] + EPS);
            g_c2[t] = (b2[t] - m2[t]) * s + be2[t];
        } else if (t < 96) {
            int o = t - 64;
            float s = g3[o] * rsqrtf(v3[o] + EPS);
            g_c3[o] = (b3[o] - m3[o]) * s + be3[o];
        } else {
            g_w4[t - 96] = W4[t - 96];
        }
    }
    if (fb == 5) {
        __shared__ int cnt[BB];
        if (t < BB) cnt[t] = 0;
        __syncthreads();
        for (int idx = t; idx < BB * NN; idx += 128)
            if (masks[idx] != 0) atomicAdd(&cnt[idx / NN], 1);
        __syncthreads();
        if (t < BB) g_active[t] = (cnt[t] > 1) ? 1 : 0;
        if (t == 64) g_b4s = b4[0];
    }
}

// ---------------- main: fused MLP via mma.sync bf16 k16, cp.async pipelined -
// Persistent blocks; tile = 8 i x 16 j; warp w = i-row (i0+w) x 16 j-cols.
__global__ __launch_bounds__(256, 2)
void k_main_mma() {
    extern __shared__ __align__(16) char sm[];
    uint4* W2s = (uint4*)(sm + OFF_W2F);
    uint4* W3s = (uint4*)(sm + OFF_W3F);
    float* c2s = (float*)(sm + OFF_C2);
    float* c3s = (float*)(sm + OFF_C3);
    float* w4s = (float*)(sm + OFF_W4);
    float* b4s = (float*)(sm + OFF_B4);

    u32 smb = s2u(sm);
    int t = threadIdx.x;
    int w = t >> 5, l = t & 31;
    int tg = l & 3, gid = l >> 2;

    {
        const uint4* s4 = (const uint4*)g_W2f;
        for (int i = t; i < 8 * 8 * 32; i += 256) W2s[i] = s4[i];
        const uint4* s3 = (const uint4*)g_W3f;
        for (int i = t; i < 4 * 4 * 32; i += 256) W3s[i] = s3[i];
        if (t < 64) c2s[t] = g_c2[t];
        if (t < 32) { c3s[t] = g_c3[t]; w4s[t] = g_w4[t]; }
        if (t == 0) b4s[0] = g_b4s;
    }

    const int NT = BB * (NN / 8) * (NN / 16);   // 4096 tiles
    const int gsz = gridDim.x;

    // stage tile -> buffer buf via cp.async (each thread: 1 U chunk + 2 V chunks)
    auto stage = [&](int tile, int buf) {
        int b   = tile >> 11;
        int rem = tile & 2047;
        int i0  = (rem >> 5) << 3;
        int j0  = (rem & 31) << 4;
        // U: 8*128 f32 contiguous = 256 x 16B
        cp16(smb + OFF_US + buf * 4096 + t * 16,
             (const char*)&g_U[((size_t)b * NN + i0) * 128] + t * 16);
        // V: 16 rows x 32 chunks, padded stride 132 f32
        #pragma unroll
        for (int q = 0; q < 2; q++) {
            int c = t + q * 256;
            int jj = c >> 5, kq = c & 31;
            cp16(smb + OFF_VS + buf * 8448 + (jj * 132 + kq * 4) * 4,
                 &g_V[((size_t)b * NN + j0 + jj) * 128 + kq * 4]);
        }
        CP_COMMIT();
    };

    int first = blockIdx.x;
    if (first < NT) stage(first, 0);

    int pidx = 0;     // parity of current tile's buffer
    for (int tile = first; tile < NT; tile += gsz, pidx ^= 1) {
        int nxt = tile + gsz;
        if (nxt < NT) { stage(nxt, pidx ^ 1); CP_WAIT(1); }
        else          { CP_WAIT(0); }
        __syncthreads();

        float* Us = (float*)(sm + OFF_US + pidx * 4096);
        float* Vs = (float*)(sm + OFF_VS + pidx * 8448);

        int b   = tile >> 11;
        int rem = tile & 2047;
        int i0  = (rem >> 5) << 3;
        int j0  = (rem & 31) << 4;

        // ---- Layer 2: C[8 nt][4], K=128 over 8 k16-steps, 3-pass bf16 ----
        float cA[8][4];
        #pragma unroll
        for (int nt = 0; nt < 8; nt++)
            #pragma unroll
            for (int q = 0; q < 4; q++) cA[nt][q] = 0.f;

        const float* urow = &Us[w * 128];
        #pragma unroll
        for (int ks = 0; ks < 8; ks++) {
            int k0 = 16 * ks + 2 * tg;
            float2 uA  = *(const float2*)&urow[k0];
            float2 uB  = *(const float2*)&urow[k0 + 8];
            float2 v0A = *(const float2*)&Vs[gid * 132 + k0];
            float2 v1A = *(const float2*)&Vs[(gid + 8) * 132 + k0];
            float2 v0B = *(const float2*)&Vs[gid * 132 + k0 + 8];
            float2 v1B = *(const float2*)&Vs[(gid + 8) * 132 + k0 + 8];
            float e00 = fmaxf(uA.x + v0A.x, 0.f), e01 = fmaxf(uA.y + v0A.y, 0.f);
            float e10 = fmaxf(uA.x + v1A.x, 0.f), e11 = fmaxf(uA.y + v1A.y, 0.f);
            float e20 = fmaxf(uB.x + v0B.x, 0.f), e21 = fmaxf(uB.y + v0B.y, 0.f);
            float e30 = fmaxf(uB.x + v1B.x, 0.f), e31 = fmaxf(uB.y + v1B.y, 0.f);
            u32 a0h = pk(e00, e01), a1h = pk(e10, e11);
            u32 a2h = pk(e20, e21), a3h = pk(e30, e31);
            u32 a0l = pk_res(e00, e01, a0h), a1l = pk_res(e10, e11, a1h);
            u32 a2l = pk_res(e20, e21, a2h), a3l = pk_res(e30, e31, a3h);
            #pragma unroll
            for (int nt = 0; nt < 8; nt++) {
                uint4 B = W2s[(ks * 8 + nt) * 32 + l];
                mma16(cA[nt], a0h, a1h, a2h, a3h, B.x, B.y);
                mma16(cA[nt], a0l, a1l, a2l, a3l, B.x, B.y);
                mma16(cA[nt], a0h, a1h, a2h, a3h, B.z, B.w);
            }
        }

        // ---- Layer 3: A-frags align with C-frags lane-exactly ----
        float cB[4][4];
        #pragma unroll
        for (int nt = 0; nt < 4; nt++)
            #pragma unroll
            for (int q = 0; q < 4; q++) cB[nt][q] = 0.f;

        #pragma unroll
        for (int ks = 0; ks < 4; ks++) {
            int n0 = 2 * ks, n1 = n0 + 1;
            float cb00 = c2s[8 * n0 + 2 * tg], cb01 = c2s[8 * n0 + 2 * tg + 1];
            float cb10 = c2s[8 * n1 + 2 * tg], cb11 = c2s[8 * n1 + 2 * tg + 1];
            float e00 = fmaxf(cA[n0][0] + cb00, 0.f), e01 = fmaxf(cA[n0][1] + cb01, 0.f);
            float e10 = fmaxf(cA[n0][2] + cb00, 0.f), e11 = fmaxf(cA[n0][3] + cb01, 0.f);
            float e20 = fmaxf(cA[n1][0] + cb10, 0.f), e21 = fmaxf(cA[n1][1] + cb11, 0.f);
            float e30 = fmaxf(cA[n1][2] + cb10, 0.f), e31 = fmaxf(cA[n1][3] + cb11, 0.f);
            u32 a0h = pk(e00, e01), a1h = pk(e10, e11);
            u32 a2h = pk(e20, e21), a3h = pk(e30, e31);
            u32 a0l = pk_res(e00, e01, a0h), a1l = pk_res(e10, e11, a1h);
            u32 a2l = pk_res(e20, e21, a2h), a3l = pk_res(e30, e31, a3h);
            #pragma unroll
            for (int nt = 0; nt < 4; nt++) {
                uint4 B = W3s[(ks * 4 + nt) * 32 + l];
                mma16(cB[nt], a0h, a1h, a2h, a3h, B.x, B.y);
                mma16(cB[nt], a0l, a1l, a2l, a3l, B.x, B.y);
                mma16(cB[nt], a0h, a1h, a2h, a3h, B.z, B.w);
            }
        }

        // ---- head: relu(+c3) dot w4, reduce across 4-lane group ----
        {
            float pl = 0.f, ph = 0.f;
            #pragma unroll
            for (int nt = 0; nt < 4; nt++) {
                int c0 = 8 * nt + 2 * tg, c1 = c0 + 1;
                float w0 = w4s[c0], w1 = w4s[c1];
                float b0 = c3s[c0], b1 = c3s[c1];
                pl += fmaxf(cB[nt][0] + b0, 0.f) * w0 + fmaxf(cB[nt][1] + b1, 0.f) * w1;
                ph += fmaxf(cB[nt][2] + b0, 0.f) * w0 + fmaxf(cB[nt][3] + b1, 0.f) * w1;
            }
            pl += __shfl_xor_sync(0xffffffffu, pl, 1);
            pl += __shfl_xor_sync(0xffffffffu, pl, 2);
            ph += __shfl_xor_sync(0xffffffffu, ph, 1);
            ph += __shfl_xor_sync(0xffffffffu, ph, 2);
            if (tg == 0) {
                float base = b4s[0];
                size_t row = ((size_t)b * NN + i0 + w) * NN + j0;
                g_L[row + gid]     = base + pl;
                g_L[row + gid + 8] = base + ph;
            }
        }
        __syncthreads();
    }
}

// ---------------- epilogue: symmetrize + sim + sigmoid + masks --------------
__global__ void k_epi(const int* __restrict__ masks, float* __restrict__ out,
                      int write_logits) {
    __shared__ float LT [32][33];
    __shared__ float nfI[32][65];
    __shared__ float nfJ[32][65];
    int b  = blockIdx.z;
    int i0 = blockIdx.y * 32;
    int j0 = blockIdx.x * 32;
    int tx = threadIdx.x, ty = threadIdx.y;

    LT[ty][tx] = g_L[((size_t)b * NN + j0 + ty) * NN + (i0 + tx)];
    nfI[ty][tx]      = g_nfn[((size_t)b * NN + i0 + ty) * DD + tx];
    nfI[ty][tx + 32] = g_nfn[((size_t)b * NN + i0 + ty) * DD + tx + 32];
    nfJ[ty][tx]      = g_nfn[((size_t)b * NN + j0 + ty) * DD + tx];
    nfJ[ty][tx + 32] = g_nfn[((size_t)b * NN + j0 + ty) * DD + tx + 32];
    __syncthreads();

    int i = i0 + ty, j = j0 + tx;
    float lij = g_L[((size_t)b * NN + i) * NN + j];
    float lji = LT[tx][ty];
    float lsym = (i == j) ? -10.f : 0.5f * (lij + lji);

    float sim = 0.f;
    #pragma unroll
    for (int d = 0; d < DD; d++) sim += nfI[ty][d] * nfJ[tx][d];

    float logit = (lsym + 2.f * sim) * 2.f;
    float p = 1.f / (1.f + expf(-logit));
    p = (p > 0.6f) ? p * 1.2f : p * 0.8f;
    p = fminf(fmaxf(p, 0.f), 1.f);

    bool m = (masks[b * NN + i] != 0) && (masks[b * NN + j] != 0) && (g_active[b] != 0);
    size_t idx = ((size_t)b * NN + i) * NN + j;
    out[idx] = m ? p : 0.f;
    if (write_logits) out[(size_t)BB * NN * NN + idx] = m ? logit : 0.f;
}

// ---------------- launch ----------------
extern "C" void kernel_launch(void* const* d_in, const int* in_sizes, int n_in,
                              void* d_out, int out_size) {
    const float* nf    = (const float*)d_in[0];
    const int*   masks = (const int*)  d_in[1];
    const float *W1, *b1, *W2, *b2, *W3, *b3, *W4, *b4;
    const float *g1, *be1, *m1, *v1, *g2, *be2, *m2, *v2, *g3, *be3, *m3, *v3;

    if (n_in >= 22 && in_sizes[4] == 8192) {
        W1 = (const float*)d_in[2];  b1 = (const float*)d_in[3];
        W2 = (const float*)d_in[4];  b2 = (const float*)d_in[5];
        W3 = (const float*)d_in[6];  b3 = (const float*)d_in[7];
        W4 = (const float*)d_in[8];  b4 = (const float*)d_in[9];
        g1 = (const float*)d_in[10]; be1 = (const float*)d_in[11];
        m1 = (const float*)d_in[12]; v1  = (const float*)d_in[13];
        g2 = (const float*)d_in[14]; be2 = (const float*)d_in[15];
        m2 = (const float*)d_in[16]; v2  = (const float*)d_in[17];
        g3 = (const float*)d_in[18]; be3 = (const float*)d_in[19];
        m3 = (const float*)d_in[20]; v3  = (const float*)d_in[21];
    } else {
        W1 = (const float*)d_in[2];  b1 = (const float*)d_in[3];
        g1 = (const float*)d_in[4];  be1 = (const float*)d_in[5];
        m1 = (const float*)d_in[6];  v1  = (const float*)d_in[7];
        W2 = (const float*)d_in[8];  b2 = (const float*)d_in[9];
        g2 = (const float*)d_in[10]; be2 = (const float*)d_in[11];
        m2 = (const float*)d_in[12]; v2  = (const float*)d_in[13];
        W3 = (const float*)d_in[14]; b3 = (const float*)d_in[15];
        g3 = (const float*)d_in[16]; be3 = (const float*)d_in[17];
        m3 = (const float*)d_in[18]; v3  = (const float*)d_in[19];
        W4 = (const float*)d_in[20]; b4 = (const float*)d_in[21];
    }

    static bool attr_set = false;
    if (!attr_set) {
        cudaFuncSetAttribute(k_main_mma, cudaFuncAttributeMaxDynamicSharedMemorySize, SMEM_MM);
        attr_set = true;
    }

    k_prep<<<BB * NN + 8, 128>>>(nf, W1, b1, g1, be1, m1, v1,
                                 W2, b2, g2, be2, m2, v2,
                                 W3, b3, g3, be3, m3, v3, W4, b4, masks);
    k_main_mma<<<296, 256, SMEM_MM>>>();
    int wl = (out_size >= 2 * BB * NN * NN) ? 1 : 0;
    k_epi<<<dim3(NN / 32, NN / 32, BB), dim3(32, 32)>>>(masks, (float*)d_out, wl);
}

// round 9
// speedup vs baseline: 2.0817x; 1.4909x over previous
#include <cuda_runtime.h>
#include <cuda_bf16.h>
#include <cstdint>
#include <math.h>

#define EPS   1e-5f
#define BB    2
#define NN    512
#define DD    64

typedef unsigned long long ull;
typedef unsigned int u32;

// ---------------- device scratch ----------------
__device__ __align__(16) float g_U   [BB*NN*128];   // s1*(W1a@f), [node][128]
__device__ __align__(16) float g_V   [BB*NN*128];   // s1*(W1b@f)+bias, [node][128]
__device__ __align__(16) float g_nfn [BB*NN*DD];
__device__ __align__(16) float g_W1t [128*128];     // [in d][out o], s1-folded
__device__ __align__(16) float g_Vb1 [128];         // (b1-m1)*s1+be1
__device__ __align__(16) uint4 g_W2f [8*8*32];      // B-frag bf16: {bh0,bh1,bl0,bl1}
__device__ __align__(16) uint4 g_W3f [4*4*32];
__device__ float g_c2[64], g_c3[32], g_w4[32], g_b4s;
__device__ __align__(16) float g_L   [BB*NN*NN];
__device__ int   g_active[BB];

// ---------------- helpers ----------------
__device__ __forceinline__ u32 pk(float e0, float e1) {
    u32 r; asm("cvt.rn.bf16x2.f32 %0, %1, %2;" : "=r"(r) : "f"(e1), "f"(e0)); return r;
}
__device__ __forceinline__ u32 pk_res(float e0, float e1, u32 h) {
    float r0 = __uint_as_float(h << 16);
    float r1 = __uint_as_float(h & 0xffff0000u);
    return pk(e0 - r0, e1 - r1);
}
__device__ __forceinline__ void mma16(float c[4], u32 a0, u32 a1, u32 a2, u32 a3,
                                      u32 b0, u32 b1) {
    asm("mma.sync.aligned.m16n8k16.row.col.f32.bf16.bf16.f32 "
        "{%0,%1,%2,%3}, {%4,%5,%6,%7}, {%8,%9}, {%0,%1,%2,%3};"
        : "+f"(c[0]), "+f"(c[1]), "+f"(c[2]), "+f"(c[3])
        : "r"(a0), "r"(a1), "r"(a2), "r"(a3), "r"(b0), "r"(b1));
}
__device__ __forceinline__ u32 s2u(const void* p) {
    u32 a;
    asm("{ .reg .u64 t; cvta.to.shared.u64 t, %1; cvt.u32.u64 %0, t; }" : "=r"(a) : "l"(p));
    return a;
}
__device__ __forceinline__ void cp16(u32 dst, const void* src) {
    asm volatile("cp.async.ca.shared.global [%0], [%1], 16;"
                 :: "r"(dst), "l"(__cvta_generic_to_global(src)) : "memory");
}
#define CP_COMMIT() asm volatile("cp.async.commit_group;" ::: "memory")
#define CP_WAIT(n)  asm volatile("cp.async.wait_group %0;" :: "n"(n) : "memory")

// ---------------- smem layout for k_main (bytes) ----------------
#define OFF_W2F  0          /* 32768 */
#define OFF_W3F  32768      /* 8192 */
#define OFF_US   40960      /* 2 bufs x 4096  = 8192  (8*128 f32)   */
#define OFF_VS   49152      /* 2 bufs x 8448  = 16896 (16*132 f32)  */
#define OFF_C2   66048      /* 256 */
#define OFF_C3   66304      /* 128 */
#define OFF_W4   66432      /* 128 */
#define OFF_B4   66560      /* 4 */
#define SMEM_MM  66576

// ---------------- setup: W1 transpose+fold, frag packing, consts, active ---
// grid: 16 transpose blocks + 8 frag blocks + 1 consts + 1 active = 26
__global__ void k_setup(const float* __restrict__ W1, const float* __restrict__ b1,
                        const float* __restrict__ g1, const float* __restrict__ be1,
                        const float* __restrict__ m1, const float* __restrict__ v1,
                        const float* __restrict__ W2, const float* __restrict__ b2,
                        const float* __restrict__ g2, const float* __restrict__ be2,
                        const float* __restrict__ m2, const float* __restrict__ v2,
                        const float* __restrict__ W3, const float* __restrict__ b3,
                        const float* __restrict__ g3, const float* __restrict__ be3,
                        const float* __restrict__ m3, const float* __restrict__ v3,
                        const float* __restrict__ W4, const float* __restrict__ b4,
                        const int* __restrict__ masks) {
    int t = threadIdx.x;
    int bid = blockIdx.x;
    if (bid < 16) {
        // transpose 32x32 tile of W1 with s1 fold: g_W1t[in][o] = W1[o][in]*s1[o]
        __shared__ float tile[32][33];
        int ti = bid >> 2, tj = bid & 3;     // o-tile, in-tile
        int tx = t & 31, ty = t >> 5;        // ty 0..7
        #pragma unroll
        for (int r = 0; r < 4; r++) {
            int o = ti * 32 + ty + 8 * r, in = tj * 32 + tx;
            tile[ty + 8 * r][tx] = W1[o * 128 + in];
        }
        __syncthreads();
        int o2 = ti * 32 + tx;
        float s1 = g1[o2] * rsqrtf(v1[o2] + EPS);
        #pragma unroll
        for (int r = 0; r < 4; r++) {
            int in2 = tj * 32 + ty + 8 * r;
            g_W1t[in2 * 128 + o2] = tile[tx][ty + 8 * r] * s1;
        }
        return;
    }
    if (bid < 24) {
        int fb = bid - 16;                   // 0..7
        int idx = fb * 256 + t;              // W2: 2048 entries exactly
        {
            int ks = idx >> 8, nt = (idx >> 5) & 7, l = idx & 31;
            int n = 8 * nt + (l >> 2), k0 = 16 * ks + 2 * (l & 3);
            float s = g2[n] * rsqrtf(v2[n] + EPS);
            float w00 = W2[n * 128 + k0] * s,     w01 = W2[n * 128 + k0 + 1] * s;
            float w10 = W2[n * 128 + k0 + 8] * s, w11 = W2[n * 128 + k0 + 9] * s;
            u32 bh0 = pk(w00, w01), bh1 = pk(w10, w11);
            g_W2f[idx] = make_uint4(bh0, bh1, pk_res(w00, w01, bh0), pk_res(w10, w11, bh1));
        }
        if (idx < 4 * 4 * 32) {              // W3: 512 entries (fb 0..1)
            int ks = idx >> 7, nt = (idx >> 5) & 3, l = idx & 31;
            int n = 8 * nt + (l >> 2), k0 = 16 * ks + 2 * (l & 3);
            float s = g3[n] * rsqrtf(v3[n] + EPS);
            float w00 = W3[n * 64 + k0] * s,     w01 = W3[n * 64 + k0 + 1] * s;
            float w10 = W3[n * 64 + k0 + 8] * s, w11 = W3[n * 64 + k0 + 9] * s;
            u32 bh0 = pk(w00, w01), bh1 = pk(w10, w11);
            g_W3f[idx] = make_uint4(bh0, bh1, pk_res(w00, w01, bh0), pk_res(w10, w11, bh1));
        }
        return;
    }
    if (bid == 24) {
        if (t < 128) {
            float s1 = g1[t] * rsqrtf(v1[t] + EPS);
            g_Vb1[t] = (b1[t] - m1[t]) * s1 + be1[t];
        } else if (t < 192) {
            int o = t - 128;
            float s = g2[o] * rsqrtf(v2[o] + EPS);
            g_c2[o] = (b2[o] - m2[o]) * s + be2[o];
        } else if (t < 224) {
            int o = t - 192;
            float s = g3[o] * rsqrtf(v3[o] + EPS);
            g_c3[o] = (b3[o] - m3[o]) * s + be3[o];
        } else {
            g_w4[t - 224] = W4[t - 224];
        }
        if (t == 0) g_b4s = b4[0];
        return;
    }
    // bid == 25: active flags
    {
        __shared__ int cnt[BB];
        if (t < BB) cnt[t] = 0;
        __syncthreads();
        for (int idx = t; idx < BB * NN; idx += 256)
            if (masks[idx] != 0) atomicAdd(&cnt[idx / NN], 1);
        __syncthreads();
        if (t < BB) g_active[t] = (cnt[t] > 1) ? 1 : 0;
    }
}

// ---------------- nodes: per-node U, V, normalized features ----------------
// 128 threads, thread t = output channel o. Reads g_W1t coalesced.
__global__ void k_nodes(const float* __restrict__ f) {
    __shared__ float fs[DD];
    __shared__ float sinv;
    int node = blockIdx.x;
    int t = threadIdx.x;
    if (t < DD) fs[t] = f[node * DD + t];
    __syncthreads();
    if (t < 32) {
        float a = fs[t], b = fs[t + 32];
        float ss = a * a + b * b;
        ss += __shfl_xor_sync(0xffffffffu, ss, 16);
        ss += __shfl_xor_sync(0xffffffffu, ss, 8);
        ss += __shfl_xor_sync(0xffffffffu, ss, 4);
        ss += __shfl_xor_sync(0xffffffffu, ss, 2);
        ss += __shfl_xor_sync(0xffffffffu, ss, 1);
        if (t == 0) sinv = 1.f / fmaxf(sqrtf(ss), 1e-12f);
    }
    __syncthreads();
    if (t < DD) g_nfn[node * DD + t] = fs[t] * sinv;

    float u = 0.f, vv = 0.f;
    #pragma unroll 8
    for (int d = 0; d < DD; d++) {
        float fd = fs[d];
        u  += g_W1t[d * 128 + t] * fd;
        vv += g_W1t[(d + DD) * 128 + t] * fd;
    }
    g_U[node * 128 + t] = u;
    g_V[node * 128 + t] = vv + g_Vb1[t];
}

// ---------------- main: fused MLP via mma.sync bf16 k16, cp.async pipelined -
__global__ __launch_bounds__(256, 2)
void k_main_mma() {
    extern __shared__ __align__(16) char sm[];
    uint4* W2s = (uint4*)(sm + OFF_W2F);
    uint4* W3s = (uint4*)(sm + OFF_W3F);
    float* c2s = (float*)(sm + OFF_C2);
    float* c3s = (float*)(sm + OFF_C3);
    float* w4s = (float*)(sm + OFF_W4);
    float* b4s = (float*)(sm + OFF_B4);

    u32 smb = s2u(sm);
    int t = threadIdx.x;
    int w = t >> 5, l = t & 31;
    int tg = l & 3, gid = l >> 2;

    {
        const uint4* s4 = (const uint4*)g_W2f;
        for (int i = t; i < 8 * 8 * 32; i += 256) W2s[i] = s4[i];
        const uint4* s3 = (const uint4*)g_W3f;
        for (int i = t; i < 4 * 4 * 32; i += 256) W3s[i] = s3[i];
        if (t < 64) c2s[t] = g_c2[t];
        if (t < 32) { c3s[t] = g_c3[t]; w4s[t] = g_w4[t]; }
        if (t == 0) b4s[0] = g_b4s;
    }

    const int NT = BB * (NN / 8) * (NN / 16);   // 4096 tiles
    const int gsz = gridDim.x;

    auto stage = [&](int tile, int buf) {
        int b   = tile >> 11;
        int rem = tile & 2047;
        int i0  = (rem >> 5) << 3;
        int j0  = (rem & 31) << 4;
        cp16(smb + OFF_US + buf * 4096 + t * 16,
             (const char*)&g_U[((size_t)b * NN + i0) * 128] + t * 16);
        #pragma unroll
        for (int q = 0; q < 2; q++) {
            int c = t + q * 256;
            int jj = c >> 5, kq = c & 31;
            cp16(smb + OFF_VS + buf * 8448 + (jj * 132 + kq * 4) * 4,
                 &g_V[((size_t)b * NN + j0 + jj) * 128 + kq * 4]);
        }
        CP_COMMIT();
    };

    int first = blockIdx.x;
    if (first < NT) stage(first, 0);

    int pidx = 0;
    for (int tile = first; tile < NT; tile += gsz, pidx ^= 1) {
        int nxt = tile + gsz;
        if (nxt < NT) { stage(nxt, pidx ^ 1); CP_WAIT(1); }
        else          { CP_WAIT(0); }
        __syncthreads();

        float* Us = (float*)(sm + OFF_US + pidx * 4096);
        float* Vs = (float*)(sm + OFF_VS + pidx * 8448);

        int b   = tile >> 11;
        int rem = tile & 2047;
        int i0  = (rem >> 5) << 3;
        int j0  = (rem & 31) << 4;

        float cA[8][4];
        #pragma unroll
        for (int nt = 0; nt < 8; nt++)
            #pragma unroll
            for (int q = 0; q < 4; q++) cA[nt][q] = 0.f;

        const float* urow = &Us[w * 128];
        #pragma unroll
        for (int ks = 0; ks < 8; ks++) {
            int k0 = 16 * ks + 2 * tg;
            float2 uA  = *(const float2*)&urow[k0];
            float2 uB  = *(const float2*)&urow[k0 + 8];
            float2 v0A = *(const float2*)&Vs[gid * 132 + k0];
            float2 v1A = *(const float2*)&Vs[(gid + 8) * 132 + k0];
            float2 v0B = *(const float2*)&Vs[gid * 132 + k0 + 8];
            float2 v1B = *(const float2*)&Vs[(gid + 8) * 132 + k0 + 8];
            float e00 = fmaxf(uA.x + v0A.x, 0.f), e01 = fmaxf(uA.y + v0A.y, 0.f);
            float e10 = fmaxf(uA.x + v1A.x, 0.f), e11 = fmaxf(uA.y + v1A.y, 0.f);
            float e20 = fmaxf(uB.x + v0B.x, 0.f), e21 = fmaxf(uB.y + v0B.y, 0.f);
            float e30 = fmaxf(uB.x + v1B.x, 0.f), e31 = fmaxf(uB.y + v1B.y, 0.f);
            u32 a0h = pk(e00, e01), a1h = pk(e10, e11);
            u32 a2h = pk(e20, e21), a3h = pk(e30, e31);
            u32 a0l = pk_res(e00, e01, a0h), a1l = pk_res(e10, e11, a1h);
            u32 a2l = pk_res(e20, e21, a2h), a3l = pk_res(e30, e31, a3h);
            #pragma unroll
            for (int nt = 0; nt < 8; nt++) {
                uint4 B = W2s[(ks * 8 + nt) * 32 + l];
                mma16(cA[nt], a0h, a1h, a2h, a3h, B.x, B.y);
                mma16(cA[nt], a0l, a1l, a2l, a3l, B.x, B.y);
                mma16(cA[nt], a0h, a1h, a2h, a3h, B.z, B.w);
            }
        }

        float cB[4][4];
        #pragma unroll
        for (int nt = 0; nt < 4; nt++)
            #pragma unroll
            for (int q = 0; q < 4; q++) cB[nt][q] = 0.f;

        #pragma unroll
        for (int ks = 0; ks < 4; ks++) {
            int n0 = 2 * ks, n1 = n0 + 1;
            float cb00 = c2s[8 * n0 + 2 * tg], cb01 = c2s[8 * n0 + 2 * tg + 1];
            float cb10 = c2s[8 * n1 + 2 * tg], cb11 = c2s[8 * n1 + 2 * tg + 1];
            float e00 = fmaxf(cA[n0][0] + cb00, 0.f), e01 = fmaxf(cA[n0][1] + cb01, 0.f);
            float e10 = fmaxf(cA[n0][2] + cb00, 0.f), e11 = fmaxf(cA[n0][3] + cb01, 0.f);
            float e20 = fmaxf(cA[n1][0] + cb10, 0.f), e21 = fmaxf(cA[n1][1] + cb11, 0.f);
            float e30 = fmaxf(cA[n1][2] + cb10, 0.f), e31 = fmaxf(cA[n1][3] + cb11, 0.f);
            u32 a0h = pk(e00, e01), a1h = pk(e10, e11);
            u32 a2h = pk(e20, e21), a3h = pk(e30, e31);
            u32 a0l = pk_res(e00, e01, a0h), a1l = pk_res(e10, e11, a1h);
            u32 a2l = pk_res(e20, e21, a2h), a3l = pk_res(e30, e31, a3h);
            #pragma unroll
            for (int nt = 0; nt < 4; nt++) {
                uint4 B = W3s[(ks * 4 + nt) * 32 + l];
                mma16(cB[nt], a0h, a1h, a2h, a3h, B.x, B.y);
                mma16(cB[nt], a0l, a1l, a2l, a3l, B.x, B.y);
                mma16(cB[nt], a0h, a1h, a2h, a3h, B.z, B.w);
            }
        }

        {
            float pl = 0.f, ph = 0.f;
            #pragma unroll
            for (int nt = 0; nt < 4; nt++) {
                int c0 = 8 * nt + 2 * tg, c1 = c0 + 1;
                float w0 = w4s[c0], w1 = w4s[c1];
                float b0 = c3s[c0], b1 = c3s[c1];
                pl += fmaxf(cB[nt][0] + b0, 0.f) * w0 + fmaxf(cB[nt][1] + b1, 0.f) * w1;
                ph += fmaxf(cB[nt][2] + b0, 0.f) * w0 + fmaxf(cB[nt][3] + b1, 0.f) * w1;
            }
            pl += __shfl_xor_sync(0xffffffffu, pl, 1);
            pl += __shfl_xor_sync(0xffffffffu, pl, 2);
            ph += __shfl_xor_sync(0xffffffffu, ph, 1);
            ph += __shfl_xor_sync(0xffffffffu, ph, 2);
            if (tg == 0) {
                float base = b4s[0];
                size_t row = ((size_t)b * NN + i0 + w) * NN + j0;
                g_L[row + gid]     = base + pl;
                g_L[row + gid + 8] = base + ph;
            }
        }
        __syncthreads();
    }
}

// ---------------- epilogue: symmetrize + sim + sigmoid + masks --------------
__global__ void k_epi(const int* __restrict__ masks, float* __restrict__ out,
                      int write_logits) {
    __shared__ float LT [32][33];
    __shared__ float nfI[32][65];
    __shared__ float nfJ[32][65];
    int b  = blockIdx.z;
    int i0 = blockIdx.y * 32;
    int j0 = blockIdx.x * 32;
    int tx = threadIdx.x, ty = threadIdx.y;

    LT[ty][tx] = g_L[((size_t)b * NN + j0 + ty) * NN + (i0 + tx)];
    nfI[ty][tx]      = g_nfn[((size_t)b * NN + i0 + ty) * DD + tx];
    nfI[ty][tx + 32] = g_nfn[((size_t)b * NN + i0 + ty) * DD + tx + 32];
    nfJ[ty][tx]      = g_nfn[((size_t)b * NN + j0 + ty) * DD + tx];
    nfJ[ty][tx + 32] = g_nfn[((size_t)b * NN + j0 + ty) * DD + tx + 32];
    __syncthreads();

    int i = i0 + ty, j = j0 + tx;
    float lij = g_L[((size_t)b * NN + i) * NN + j];
    float lji = LT[tx][ty];
    float lsym = (i == j) ? -10.f : 0.5f * (lij + lji);

    float sim = 0.f;
    #pragma unroll
    for (int d = 0; d < DD; d++) sim += nfI[ty][d] * nfJ[tx][d];

    float logit = (lsym + 2.f * sim) * 2.f;
    float p = 1.f / (1.f + expf(-logit));
    p = (p > 0.6f) ? p * 1.2f : p * 0.8f;
    p = fminf(fmaxf(p, 0.f), 1.f);

    bool m = (masks[b * NN + i] != 0) && (masks[b * NN + j] != 0) && (g_active[b] != 0);
    size_t idx = ((size_t)b * NN + i) * NN + j;
    out[idx] = m ? p : 0.f;
    if (write_logits) out[(size_t)BB * NN * NN + idx] = m ? logit : 0.f;
}

// ---------------- launch ----------------
extern "C" void kernel_launch(void* const* d_in, const int* in_sizes, int n_in,
                              void* d_out, int out_size) {
    const float* nf    = (const float*)d_in[0];
    const int*   masks = (const int*)  d_in[1];
    const float *W1, *b1, *W2, *b2, *W3, *b3, *W4, *b4;
    const float *g1, *be1, *m1, *v1, *g2, *be2, *m2, *v2, *g3, *be3, *m3, *v3;

    if (n_in >= 22 && in_sizes[4] == 8192) {
        W1 = (const float*)d_in[2];  b1 = (const float*)d_in[3];
        W2 = (const float*)d_in[4];  b2 = (const float*)d_in[5];
        W3 = (const float*)d_in[6];  b3 = (const float*)d_in[7];
        W4 = (const float*)d_in[8];  b4 = (const float*)d_in[9];
        g1 = (const float*)d_in[10]; be1 = (const float*)d_in[11];
        m1 = (const float*)d_in[12]; v1  = (const float*)d_in[13];
        g2 = (const float*)d_in[14]; be2 = (const float*)d_in[15];
        m2 = (const float*)d_in[16]; v2  = (const float*)d_in[17];
        g3 = (const float*)d_in[18]; be3 = (const float*)d_in[19];
        m3 = (const float*)d_in[20]; v3  = (const float*)d_in[21];
    } else {
        W1 = (const float*)d_in[2];  b1 = (const float*)d_in[3];
        g1 = (const float*)d_in[4];  be1 = (const float*)d_in[5];
        m1 = (const float*)d_in[6];  v1  = (const float*)d_in[7];
        W2 = (const float*)d_in[8];  b2 = (const float*)d_in[9];
        g2 = (const float*)d_in[10]; be2 = (const float*)d_in[11];
        m2 = (const float*)d_in[12]; v2  = (const float*)d_in[13];
        W3 = (const float*)d_in[14]; b3 = (const float*)d_in[15];
        g3 = (const float*)d_in[16]; be3 = (const float*)d_in[17];
        m3 = (const float*)d_in[18]; v3  = (const float*)d_in[19];
        W4 = (const float*)d_in[20]; b4 = (const float*)d_in[21];
    }

    static bool attr_set = false;
    if (!attr_set) {
        cudaFuncSetAttribute(k_main_mma, cudaFuncAttributeMaxDynamicSharedMemorySize, SMEM_MM);
        attr_set = true;
    }

    k_setup<<<26, 256>>>(W1, b1, g1, be1, m1, v1,
                         W2, b2, g2, be2, m2, v2,
                         W3, b3, g3, be3, m3, v3, W4, b4, masks);
    k_nodes<<<BB * NN, 128>>>(nf);
    k_main_mma<<<296, 256, SMEM_MM>>>();
    int wl = (out_size >= 2 * BB * NN * NN) ? 1 : 0;
    k_epi<<<dim3(NN / 32, NN / 32, BB), dim3(32, 32)>>>(masks, (float*)d_out, wl);
}